// round 2
// baseline (speedup 1.0000x reference)
#include <cuda_runtime.h>
#include <math.h>

// Problem constants
constexpr int D    = 768;
constexpr int SQ   = 2048;
constexpr int BATCH = 4;
constexpr int NH   = 12;
constexpr int HDIM = 64;
constexpr int MTOT = BATCH * SQ;   // 8192 rows

// Scratch (alloc-free rule: __device__ globals)
__device__ float g_Q[MTOT * D];
__device__ float g_K[MTOT * D];
__device__ float g_V[MTOT * D];
__device__ float g_ctx[MTOT * D];

// ---------------------------------------------------------------------------
// GEMM: C[m][n] = sum_k A[m][k] * W[n][k] + bias[n]   (torch Linear semantics)
// M=8192, N=768, K=768. BM=BN=64, BK=16, 256 threads, 4x4 per thread.
// ---------------------------------------------------------------------------
constexpr int BM = 64, BN = 64, BK = 16, PAD = 68;

__device__ __forceinline__ void gemm_nt(const float* __restrict__ A,
                                        const float* __restrict__ W,
                                        const float* __restrict__ bias,
                                        float* __restrict__ C) {
    __shared__ float As[BK][PAD];   // [k][m]
    __shared__ float Bs[BK][PAD];   // [k][n]
    const int tid = threadIdx.x;
    const int tx = tid & 15, ty = tid >> 4;
    const int m0 = blockIdx.y * BM, n0 = blockIdx.x * BN;
    const int lm = tid >> 2;          // 0..63
    const int lk = (tid & 3) * 4;     // 0,4,8,12
    const float* Ap = A + (size_t)(m0 + lm) * D + lk;
    const float* Wp = W + (size_t)(n0 + lm) * D + lk;
    float acc[4][4] = {};
    for (int kt = 0; kt < D; kt += BK) {
        float4 av = *(const float4*)(Ap + kt);
        float4 wv = *(const float4*)(Wp + kt);
        As[lk + 0][lm] = av.x; As[lk + 1][lm] = av.y;
        As[lk + 2][lm] = av.z; As[lk + 3][lm] = av.w;
        Bs[lk + 0][lm] = wv.x; Bs[lk + 1][lm] = wv.y;
        Bs[lk + 2][lm] = wv.z; Bs[lk + 3][lm] = wv.w;
        __syncthreads();
#pragma unroll
        for (int kk = 0; kk < BK; kk++) {
            float4 a = *(const float4*)&As[kk][ty * 4];
            float4 b = *(const float4*)&Bs[kk][tx * 4];
            float af[4] = {a.x, a.y, a.z, a.w};
            float bf[4] = {b.x, b.y, b.z, b.w};
#pragma unroll
            for (int i = 0; i < 4; i++)
#pragma unroll
                for (int j = 0; j < 4; j++)
                    acc[i][j] = fmaf(af[i], bf[j], acc[i][j]);
        }
        __syncthreads();
    }
    float bb[4];
#pragma unroll
    for (int j = 0; j < 4; j++) bb[j] = bias[n0 + tx * 4 + j];
#pragma unroll
    for (int i = 0; i < 4; i++) {
        float4 o = make_float4(acc[i][0] + bb[0], acc[i][1] + bb[1],
                               acc[i][2] + bb[2], acc[i][3] + bb[3]);
        *(float4*)&C[(size_t)(m0 + ty * 4 + i) * D + n0 + tx * 4] = o;
    }
}

__global__ void __launch_bounds__(256)
qkv_gemm(const float* __restrict__ x,
         const float* __restrict__ Wq, const float* __restrict__ bq,
         const float* __restrict__ Wk, const float* __restrict__ bk,
         const float* __restrict__ Wv, const float* __restrict__ bv) {
    const float* W; const float* bias; float* C;
    if (blockIdx.z == 0)      { W = Wq; bias = bq; C = g_Q; }
    else if (blockIdx.z == 1) { W = Wk; bias = bk; C = g_K; }
    else                      { W = Wv; bias = bv; C = g_V; }
    gemm_nt(x, W, bias, C);
}

__global__ void __launch_bounds__(256)
out_gemm(const float* __restrict__ Wo, const float* __restrict__ bo,
         float* __restrict__ out) {
    gemm_nt(g_ctx, Wo, bo, out);
}

// ---------------------------------------------------------------------------
// Flash-style attention: grid (32 q-tiles, 48 bh), 256 threads.
// BM=64 q-rows per block, BN=64 kv per iteration, hd=64.
// Q/K stored d-major in smem, V row-major, S tile in smem; online softmax.
// O accumulator (4x4 per thread) is register-resident across the kv loop.
// ---------------------------------------------------------------------------
constexpr int TPAD = 68;
constexpr int ATTN_SMEM_FLOATS = 4 * 64 * TPAD + 128;
constexpr int ATTN_SMEM_BYTES  = ATTN_SMEM_FLOATS * 4;   // 70144 B

__global__ void __launch_bounds__(256)
attn_kernel() {
    extern __shared__ float sm[];
    float* Qs = sm;                    // [d][r], d-major, pad 68
    float* Ks = sm + 64 * TPAD;        // [d][c]
    float* Vs = sm + 2 * 64 * TPAD;    // [j][d]
    float* Ss = sm + 3 * 64 * TPAD;    // [r][c]
    float* alpha_s = sm + 4 * 64 * TPAD;   // [64]
    float* l_s     = alpha_s + 64;         // [64]

    const int tid = threadIdx.x;
    const int tx = tid & 15, ty = tid >> 4;
    const int bh = blockIdx.y;                  // 0..47
    const int b = bh / NH, h = bh % NH;
    const int q0 = blockIdx.x * 64;

    const float* Qb = g_Q + (size_t)(b * SQ) * D + h * HDIM;
    const float* Kb = g_K + (size_t)(b * SQ) * D + h * HDIM;
    const float* Vb = g_V + (size_t)(b * SQ) * D + h * HDIM;

    const int lr  = tid >> 2;          // 0..63 (row/col for tile loads)
    const int ld0 = (tid & 3) * 16;    // 0,16,32,48 (d-quarter)

    // Load Q tile, transposed to d-major, fold in 1/sqrt(hd)=0.125
    {
        const float* qrow = Qb + (size_t)(q0 + lr) * D + ld0;
#pragma unroll
        for (int i4 = 0; i4 < 4; i4++) {
            float4 v = *(const float4*)(qrow + i4 * 4);
            int d = ld0 + i4 * 4;
            Qs[(d + 0) * TPAD + lr] = v.x * 0.125f;
            Qs[(d + 1) * TPAD + lr] = v.y * 0.125f;
            Qs[(d + 2) * TPAD + lr] = v.z * 0.125f;
            Qs[(d + 3) * TPAD + lr] = v.w * 0.125f;
        }
    }

    float m_team = -INFINITY, l_team = 0.0f;
    float acc[4][4] = {};
    __syncthreads();

    for (int kt = 0; kt < SQ; kt += 64) {
        // Load K (transposed to d-major) and V (row-major)
        {
            const float* krow = Kb + (size_t)(kt + lr) * D + ld0;
            const float* vrow = Vb + (size_t)(kt + lr) * D + ld0;
#pragma unroll
            for (int i4 = 0; i4 < 4; i4++) {
                float4 kv = *(const float4*)(krow + i4 * 4);
                int d = ld0 + i4 * 4;
                Ks[(d + 0) * TPAD + lr] = kv.x;
                Ks[(d + 1) * TPAD + lr] = kv.y;
                Ks[(d + 2) * TPAD + lr] = kv.z;
                Ks[(d + 3) * TPAD + lr] = kv.w;
                float4 vv = *(const float4*)(vrow + i4 * 4);
                *(float4*)&Vs[lr * TPAD + ld0 + i4 * 4] = vv;
            }
        }
        __syncthreads();

        // Phase A: S = (Q*scale) @ K^T  (4x4 register tile per thread)
        {
            float s[4][4] = {};
#pragma unroll
            for (int d = 0; d < 64; d++) {
                float4 a = *(const float4*)&Qs[d * TPAD + ty * 4];
                float4 bq = *(const float4*)&Ks[d * TPAD + tx * 4];
                float af[4] = {a.x, a.y, a.z, a.w};
                float bf[4] = {bq.x, bq.y, bq.z, bq.w};
#pragma unroll
                for (int i = 0; i < 4; i++)
#pragma unroll
                    for (int j = 0; j < 4; j++)
                        s[i][j] = fmaf(af[i], bf[j], s[i][j]);
            }
#pragma unroll
            for (int i = 0; i < 4; i++)
                *(float4*)&Ss[(ty * 4 + i) * TPAD + tx * 4] =
                    make_float4(s[i][0], s[i][1], s[i][2], s[i][3]);
        }
        __syncthreads();

        // Online softmax: 4 lanes per row (r = tid>>2, q-quarter = tid&3)
        {
            const int r = tid >> 2, qq = tid & 3;
            float p[16];
            float mloc = -INFINITY;
#pragma unroll
            for (int i4 = 0; i4 < 4; i4++) {
                float4 sv = *(const float4*)&Ss[r * TPAD + qq * 16 + i4 * 4];
                p[i4 * 4 + 0] = sv.x; p[i4 * 4 + 1] = sv.y;
                p[i4 * 4 + 2] = sv.z; p[i4 * 4 + 3] = sv.w;
                mloc = fmaxf(mloc, fmaxf(fmaxf(sv.x, sv.y), fmaxf(sv.z, sv.w)));
            }
            mloc = fmaxf(mloc, __shfl_xor_sync(0xffffffffu, mloc, 1));
            mloc = fmaxf(mloc, __shfl_xor_sync(0xffffffffu, mloc, 2));
            float m_new = fmaxf(m_team, mloc);
            float alpha = __expf(m_team - m_new);
            float lsum = 0.0f;
#pragma unroll
            for (int i = 0; i < 16; i++) {
                p[i] = __expf(p[i] - m_new);
                lsum += p[i];
            }
            lsum += __shfl_xor_sync(0xffffffffu, lsum, 1);
            lsum += __shfl_xor_sync(0xffffffffu, lsum, 2);
            l_team = l_team * alpha + lsum;
            m_team = m_new;
#pragma unroll
            for (int i4 = 0; i4 < 4; i4++)
                *(float4*)&Ss[r * TPAD + qq * 16 + i4 * 4] =
                    make_float4(p[i4 * 4 + 0], p[i4 * 4 + 1],
                                p[i4 * 4 + 2], p[i4 * 4 + 3]);
            if (qq == 0) alpha_s[r] = alpha;
        }
        __syncthreads();

        // Phase C: O = O*alpha + P @ V  (register-resident accumulator)
        {
#pragma unroll
            for (int i = 0; i < 4; i++) {
                float al = alpha_s[ty * 4 + i];
                acc[i][0] *= al; acc[i][1] *= al;
                acc[i][2] *= al; acc[i][3] *= al;
            }
#pragma unroll
            for (int j = 0; j < 64; j++) {
                float4 v = *(const float4*)&Vs[j * TPAD + tx * 4];
#pragma unroll
                for (int i = 0; i < 4; i++) {
                    float pp = Ss[(ty * 4 + i) * TPAD + j];
                    acc[i][0] = fmaf(pp, v.x, acc[i][0]);
                    acc[i][1] = fmaf(pp, v.y, acc[i][1]);
                    acc[i][2] = fmaf(pp, v.z, acc[i][2]);
                    acc[i][3] = fmaf(pp, v.w, acc[i][3]);
                }
            }
        }
        __syncthreads();   // protect Ks/Vs/Ss/alpha_s for next tile
    }

    // Final normalize + store to ctx ([b,s,h*64+d] layout for O-projection)
    {
        const int r = tid >> 2, qq = tid & 3;
        if (qq == 0) l_s[r] = l_team;
    }
    __syncthreads();
    float* Ob = g_ctx + (size_t)(b * SQ + q0) * D + h * HDIM;
#pragma unroll
    for (int i = 0; i < 4; i++) {
        float inv = 1.0f / l_s[ty * 4 + i];
        float4 o = make_float4(acc[i][0] * inv, acc[i][1] * inv,
                               acc[i][2] * inv, acc[i][3] * inv);
        *(float4*)&Ob[(size_t)(ty * 4 + i) * D + tx * 4] = o;
    }
}

// ---------------------------------------------------------------------------
extern "C" void kernel_launch(void* const* d_in, const int* in_sizes, int n_in,
                              void* d_out, int out_size) {
    const float* x    = (const float*)d_in[0];
    const float* QW_w = (const float*)d_in[1];
    const float* QW_b = (const float*)d_in[2];
    const float* KW_w = (const float*)d_in[3];
    const float* KW_b = (const float*)d_in[4];
    const float* VW_w = (const float*)d_in[5];
    const float* VW_b = (const float*)d_in[6];
    const float* OW_w = (const float*)d_in[7];
    const float* OW_b = (const float*)d_in[8];
    float* out = (float*)d_out;

    // Attention kernel needs >48KB dynamic smem; set attribute (idempotent,
    // not a stream op, capture-safe).
    cudaFuncSetAttribute(attn_kernel,
                         cudaFuncAttributeMaxDynamicSharedMemorySize,
                         ATTN_SMEM_BYTES);

    dim3 gq(D / BN, MTOT / BM, 3);     // (12, 128, 3)
    qkv_gemm<<<gq, 256>>>(x, QW_w, QW_b, KW_w, KW_b, VW_w, VW_b);

    dim3 ga(SQ / 64, BATCH * NH);      // (32, 48)
    attn_kernel<<<ga, 256, ATTN_SMEM_BYTES>>>();

    dim3 go(D / BN, MTOT / BM);        // (12, 128)
    out_gemm<<<go, 256>>>(OW_w, OW_b, out);
}

// round 3
// speedup vs baseline: 1.1820x; 1.1820x over previous
#include <cuda_runtime.h>
#include <math.h>

// Problem constants
constexpr int D     = 768;
constexpr int SQ    = 2048;
constexpr int BATCH = 4;
constexpr int NH    = 12;
constexpr int HDIM  = 64;
constexpr int MTOT  = BATCH * SQ;   // 8192 rows

// Scratch (alloc-free rule: __device__ globals)
__device__ float g_Q[MTOT * D];
__device__ float g_K[MTOT * D];
__device__ float g_V[MTOT * D];
__device__ float g_ctx[MTOT * D];

// ---------------------------------------------------------------------------
// GEMM: C[m][n] = sum_k A[m][k] * W[n][k] + bias[n]   (torch Linear semantics)
// M=8192, N=768, K=768. BM=BN=128, BK=16, 256 threads, 8x8 per thread.
// Software-pipelined: prefetch next k-tile into registers during compute.
// ---------------------------------------------------------------------------
constexpr int BM = 128, BN = 128, BK = 16, BMP = 132;

__device__ __forceinline__ void gemm_nt(const float* __restrict__ A,
                                        const float* __restrict__ W,
                                        const float* __restrict__ bias,
                                        float* __restrict__ C) {
    __shared__ float As[BK][BMP];   // [k][m]
    __shared__ float Bs[BK][BMP];   // [k][n]
    const int tid = threadIdx.x;
    const int tx = tid & 15, ty = tid >> 4;
    const int m0 = blockIdx.y * BM, n0 = blockIdx.x * BN;
    const int lm = tid >> 1;          // 0..127
    const int lk = (tid & 1) * 8;     // 0 or 8
    const float* Ap = A + (size_t)(m0 + lm) * D + lk;
    const float* Wp = W + (size_t)(n0 + lm) * D + lk;

    float acc[8][8] = {};
    float4 ra0 = *(const float4*)(Ap);
    float4 ra1 = *(const float4*)(Ap + 4);
    float4 rb0 = *(const float4*)(Wp);
    float4 rb1 = *(const float4*)(Wp + 4);

    for (int kt = 0; kt < D; kt += BK) {
        As[lk + 0][lm] = ra0.x; As[lk + 1][lm] = ra0.y;
        As[lk + 2][lm] = ra0.z; As[lk + 3][lm] = ra0.w;
        As[lk + 4][lm] = ra1.x; As[lk + 5][lm] = ra1.y;
        As[lk + 6][lm] = ra1.z; As[lk + 7][lm] = ra1.w;
        Bs[lk + 0][lm] = rb0.x; Bs[lk + 1][lm] = rb0.y;
        Bs[lk + 2][lm] = rb0.z; Bs[lk + 3][lm] = rb0.w;
        Bs[lk + 4][lm] = rb1.x; Bs[lk + 5][lm] = rb1.y;
        Bs[lk + 6][lm] = rb1.z; Bs[lk + 7][lm] = rb1.w;
        __syncthreads();
        if (kt + BK < D) {   // prefetch next tile (latency hidden by compute)
            ra0 = *(const float4*)(Ap + kt + BK);
            ra1 = *(const float4*)(Ap + kt + BK + 4);
            rb0 = *(const float4*)(Wp + kt + BK);
            rb1 = *(const float4*)(Wp + kt + BK + 4);
        }
#pragma unroll
        for (int kk = 0; kk < BK; kk++) {
            float a[8], b[8];
            float4 t;
            t = *(const float4*)&As[kk][ty * 8];     a[0]=t.x; a[1]=t.y; a[2]=t.z; a[3]=t.w;
            t = *(const float4*)&As[kk][ty * 8 + 4]; a[4]=t.x; a[5]=t.y; a[6]=t.z; a[7]=t.w;
            t = *(const float4*)&Bs[kk][tx * 8];     b[0]=t.x; b[1]=t.y; b[2]=t.z; b[3]=t.w;
            t = *(const float4*)&Bs[kk][tx * 8 + 4]; b[4]=t.x; b[5]=t.y; b[6]=t.z; b[7]=t.w;
#pragma unroll
            for (int i = 0; i < 8; i++)
#pragma unroll
                for (int j = 0; j < 8; j++)
                    acc[i][j] = fmaf(a[i], b[j], acc[i][j]);
        }
        __syncthreads();
    }

    float bb[8];
#pragma unroll
    for (int j = 0; j < 8; j++) bb[j] = bias[n0 + tx * 8 + j];
#pragma unroll
    for (int i = 0; i < 8; i++) {
        float* crow = C + (size_t)(m0 + ty * 8 + i) * D + n0 + tx * 8;
        *(float4*)(crow)     = make_float4(acc[i][0] + bb[0], acc[i][1] + bb[1],
                                           acc[i][2] + bb[2], acc[i][3] + bb[3]);
        *(float4*)(crow + 4) = make_float4(acc[i][4] + bb[4], acc[i][5] + bb[5],
                                           acc[i][6] + bb[6], acc[i][7] + bb[7]);
    }
}

__global__ void __launch_bounds__(256)
qkv_gemm(const float* __restrict__ x,
         const float* __restrict__ Wq, const float* __restrict__ bq,
         const float* __restrict__ Wk, const float* __restrict__ bk,
         const float* __restrict__ Wv, const float* __restrict__ bv) {
    const float* W; const float* bias; float* C;
    if (blockIdx.z == 0)      { W = Wq; bias = bq; C = g_Q; }
    else if (blockIdx.z == 1) { W = Wk; bias = bk; C = g_K; }
    else                      { W = Wv; bias = bv; C = g_V; }
    gemm_nt(x, W, bias, C);
}

__global__ void __launch_bounds__(256)
out_gemm(const float* __restrict__ Wo, const float* __restrict__ bo,
         float* __restrict__ out) {
    gemm_nt(g_ctx, Wo, bo, out);
}

// ---------------------------------------------------------------------------
// Flash-style attention: grid (16 q-tiles, 48 bh), 256 threads.
// BMA=128 q-rows per block, BNA=64 kv per iteration, hd=64.
// 8x4 microtile in both matmul phases; online softmax 2 threads/row.
// ---------------------------------------------------------------------------
constexpr int QP = 132;   // Qs row pad (128 rows of q, d-major)
constexpr int KP = 68;    // Ks/Vs pad
constexpr int SP = 68;    // Ss pad (64 cols)
constexpr int ATTN_SMEM_FLOATS = 64 * QP + 64 * KP + 64 * KP + 128 * SP + 256;
constexpr int ATTN_SMEM_BYTES  = ATTN_SMEM_FLOATS * 4;   // 104448 B

__global__ void __launch_bounds__(256)
attn_kernel() {
    extern __shared__ float sm[];
    float* Qs = sm;                                // [d][r] d-major, 128 rows
    float* Ks = Qs + 64 * QP;                      // [d][c] d-major, 64 cols
    float* Vs = Ks + 64 * KP;                      // [j][d] row-major
    float* Ss = Vs + 64 * KP;                      // [r][c] 128x64
    float* alpha_s = Ss + 128 * SP;                // [128]
    float* l_s     = alpha_s + 128;                // [128]

    const int tid = threadIdx.x;
    const int tx = tid & 15, ty = tid >> 4;
    const int bh = blockIdx.y;                     // 0..47
    const int b = bh / NH, h = bh % NH;
    const int q0 = blockIdx.x * 128;

    const float* Qb = g_Q + (size_t)(b * SQ) * D + h * HDIM;
    const float* Kb = g_K + (size_t)(b * SQ) * D + h * HDIM;
    const float* Vb = g_V + (size_t)(b * SQ) * D + h * HDIM;

    // Load Q tile (128 x 64), transposed to d-major, fold in 1/sqrt(64)=0.125
    {
        const int lr = tid >> 1;               // 0..127
        const int ld0 = (tid & 1) * 32;        // 0 or 32
        const float* qrow = Qb + (size_t)(q0 + lr) * D + ld0;
#pragma unroll
        for (int i4 = 0; i4 < 8; i4++) {
            float4 v = *(const float4*)(qrow + i4 * 4);
            int d = ld0 + i4 * 4;
            Qs[(d + 0) * QP + lr] = v.x * 0.125f;
            Qs[(d + 1) * QP + lr] = v.y * 0.125f;
            Qs[(d + 2) * QP + lr] = v.z * 0.125f;
            Qs[(d + 3) * QP + lr] = v.w * 0.125f;
        }
    }

    float m_team = -INFINITY, l_team = 0.0f;   // per-row state (row = tid>>1)
    float acc[8][4] = {};
    __syncthreads();

    for (int kt = 0; kt < SQ; kt += 64) {
        // Load K (d-major) and V (row-major): 64 rows x 64 d
        {
            const int lr = tid >> 2;           // 0..63
            const int ld0 = (tid & 3) * 16;    // 0,16,32,48
            const float* krow = Kb + (size_t)(kt + lr) * D + ld0;
            const float* vrow = Vb + (size_t)(kt + lr) * D + ld0;
#pragma unroll
            for (int i4 = 0; i4 < 4; i4++) {
                float4 kv = *(const float4*)(krow + i4 * 4);
                int d = ld0 + i4 * 4;
                Ks[(d + 0) * KP + lr] = kv.x;
                Ks[(d + 1) * KP + lr] = kv.y;
                Ks[(d + 2) * KP + lr] = kv.z;
                Ks[(d + 3) * KP + lr] = kv.w;
                float4 vv = *(const float4*)(vrow + i4 * 4);
                *(float4*)&Vs[lr * KP + ld0 + i4 * 4] = vv;
            }
        }
        __syncthreads();

        // Phase A: S = (Q*scale) @ K^T   (8x4 per thread)
        {
            float s[8][4] = {};
#pragma unroll
            for (int d = 0; d < 64; d++) {
                float a[8];
                float4 t;
                t = *(const float4*)&Qs[d * QP + ty * 8];     a[0]=t.x; a[1]=t.y; a[2]=t.z; a[3]=t.w;
                t = *(const float4*)&Qs[d * QP + ty * 8 + 4]; a[4]=t.x; a[5]=t.y; a[6]=t.z; a[7]=t.w;
                float4 kv = *(const float4*)&Ks[d * KP + tx * 4];
#pragma unroll
                for (int i = 0; i < 8; i++) {
                    s[i][0] = fmaf(a[i], kv.x, s[i][0]);
                    s[i][1] = fmaf(a[i], kv.y, s[i][1]);
                    s[i][2] = fmaf(a[i], kv.z, s[i][2]);
                    s[i][3] = fmaf(a[i], kv.w, s[i][3]);
                }
            }
#pragma unroll
            for (int i = 0; i < 8; i++)
                *(float4*)&Ss[(ty * 8 + i) * SP + tx * 4] =
                    make_float4(s[i][0], s[i][1], s[i][2], s[i][3]);
        }
        __syncthreads();

        // Online softmax: row r = tid>>1, half = tid&1 handles 32 cols
        {
            const int r = tid >> 1, half = tid & 1;
            float* base = &Ss[r * SP + half * 32];
            float p[32];
            float mloc = -INFINITY;
#pragma unroll
            for (int i4 = 0; i4 < 8; i4++) {
                float4 sv = *(const float4*)(base + i4 * 4);
                p[i4 * 4 + 0] = sv.x; p[i4 * 4 + 1] = sv.y;
                p[i4 * 4 + 2] = sv.z; p[i4 * 4 + 3] = sv.w;
                mloc = fmaxf(mloc, fmaxf(fmaxf(sv.x, sv.y), fmaxf(sv.z, sv.w)));
            }
            mloc = fmaxf(mloc, __shfl_xor_sync(0xffffffffu, mloc, 1));
            float m_new = fmaxf(m_team, mloc);
            float alpha = __expf(m_team - m_new);
            float lsum = 0.0f;
#pragma unroll
            for (int i = 0; i < 32; i++) {
                p[i] = __expf(p[i] - m_new);
                lsum += p[i];
            }
            lsum += __shfl_xor_sync(0xffffffffu, lsum, 1);
            l_team = l_team * alpha + lsum;
            m_team = m_new;
#pragma unroll
            for (int i4 = 0; i4 < 8; i4++)
                *(float4*)(base + i4 * 4) =
                    make_float4(p[i4 * 4 + 0], p[i4 * 4 + 1],
                                p[i4 * 4 + 2], p[i4 * 4 + 3]);
            if (half == 0) alpha_s[r] = alpha;
        }
        __syncthreads();

        // Phase C: O = O*alpha + P @ V  (8x4 register accumulator)
        {
#pragma unroll
            for (int i = 0; i < 8; i++) {
                float al = alpha_s[ty * 8 + i];
                acc[i][0] *= al; acc[i][1] *= al;
                acc[i][2] *= al; acc[i][3] *= al;
            }
#pragma unroll
            for (int j = 0; j < 64; j++) {
                float4 v = *(const float4*)&Vs[j * KP + tx * 4];
#pragma unroll
                for (int i = 0; i < 8; i++) {
                    float pp = Ss[(ty * 8 + i) * SP + j];
                    acc[i][0] = fmaf(pp, v.x, acc[i][0]);
                    acc[i][1] = fmaf(pp, v.y, acc[i][1]);
                    acc[i][2] = fmaf(pp, v.z, acc[i][2]);
                    acc[i][3] = fmaf(pp, v.w, acc[i][3]);
                }
            }
        }
        __syncthreads();   // protect Ks/Vs/Ss/alpha_s for next tile
    }

    // Final normalize + store to ctx ([b,s,h*64+d] layout for O-projection)
    if ((tid & 1) == 0) l_s[tid >> 1] = l_team;
    __syncthreads();
    float* Ob = g_ctx + (size_t)(b * SQ + q0) * D + h * HDIM;
#pragma unroll
    for (int i = 0; i < 8; i++) {
        float inv = 1.0f / l_s[ty * 8 + i];
        *(float4*)&Ob[(size_t)(ty * 8 + i) * D + tx * 4] =
            make_float4(acc[i][0] * inv, acc[i][1] * inv,
                        acc[i][2] * inv, acc[i][3] * inv);
    }
}

// ---------------------------------------------------------------------------
extern "C" void kernel_launch(void* const* d_in, const int* in_sizes, int n_in,
                              void* d_out, int out_size) {
    const float* x    = (const float*)d_in[0];
    const float* QW_w = (const float*)d_in[1];
    const float* QW_b = (const float*)d_in[2];
    const float* KW_w = (const float*)d_in[3];
    const float* KW_b = (const float*)d_in[4];
    const float* VW_w = (const float*)d_in[5];
    const float* VW_b = (const float*)d_in[6];
    const float* OW_w = (const float*)d_in[7];
    const float* OW_b = (const float*)d_in[8];
    float* out = (float*)d_out;

    cudaFuncSetAttribute(attn_kernel,
                         cudaFuncAttributeMaxDynamicSharedMemorySize,
                         ATTN_SMEM_BYTES);

    dim3 gq(D / BN, MTOT / BM, 3);     // (6, 64, 3)
    qkv_gemm<<<gq, 256>>>(x, QW_w, QW_b, KW_w, KW_b, VW_w, VW_b);

    dim3 ga(SQ / 128, BATCH * NH);     // (16, 48)
    attn_kernel<<<ga, 256, ATTN_SMEM_BYTES>>>();

    dim3 go(D / BN, MTOT / BM);        // (6, 64)
    out_gemm<<<go, 256>>>(OW_w, OW_b, out);
}